// round 3
// baseline (speedup 1.0000x reference)
#include <cuda_runtime.h>
#include <stdint.h>

#define PW_SMEM_CAP 2048

// out[i] = Param_b[b_params[i]]  (bias init, also clears the 0xAA poison)
__global__ void bias_init_kernel(const float* __restrict__ Param_b,
                                 const int* __restrict__ b_params,
                                 float* __restrict__ out, int n) {
    int i = blockIdx.x * blockDim.x + threadIdx.x;
    if (i < n) {
        out[i] = __ldg(&Param_b[b_params[i]]);
    }
}

// 8 edges per thread (2 x int4 per index stream).
// Param_W staged in shared memory; index streams loaded with streaming hint
// (__ldcs) to avoid polluting L1, which we want to keep for x gathers.
__global__ void __launch_bounds__(256) edge_scatter_kernel(
        const float* __restrict__ x,
        const float* __restrict__ Param_W,
        const int4* __restrict__ w_rows4,
        const int4* __restrict__ w_cols4,
        const int4* __restrict__ w_params4,
        float* __restrict__ out, int e4, int npw) {
    __shared__ float s_pw[PW_SMEM_CAP];
    const bool use_smem = (npw <= PW_SMEM_CAP);
    if (use_smem) {
        for (int i = threadIdx.x; i < npw; i += blockDim.x)
            s_pw[i] = Param_W[i];
        __syncthreads();
    }

    int t = blockIdx.x * blockDim.x + threadIdx.x;
    int i0 = t * 2;
    int i1 = i0 + 1;
    if (i0 >= e4) return;

    // --- group 0 ---
    int4 r0 = __ldcs(&w_rows4[i0]);
    int4 c0 = __ldcs(&w_cols4[i0]);
    int4 p0 = __ldcs(&w_params4[i0]);
    // --- group 1 (may be out of range) ---
    bool has1 = (i1 < e4);
    int4 r1, c1, p1;
    if (has1) {
        r1 = __ldcs(&w_rows4[i1]);
        c1 = __ldcs(&w_cols4[i1]);
        p1 = __ldcs(&w_params4[i1]);
    }

    // gathers for group 0 (x via L1-cached path)
    float x00 = __ldg(&x[c0.x]);
    float x01 = __ldg(&x[c0.y]);
    float x02 = __ldg(&x[c0.z]);
    float x03 = __ldg(&x[c0.w]);
    float w00, w01, w02, w03;
    if (use_smem) {
        w00 = s_pw[p0.x]; w01 = s_pw[p0.y]; w02 = s_pw[p0.z]; w03 = s_pw[p0.w];
    } else {
        w00 = __ldg(&Param_W[p0.x]); w01 = __ldg(&Param_W[p0.y]);
        w02 = __ldg(&Param_W[p0.z]); w03 = __ldg(&Param_W[p0.w]);
    }

    float x10, x11, x12, x13, w10, w11, w12, w13;
    if (has1) {
        x10 = __ldg(&x[c1.x]);
        x11 = __ldg(&x[c1.y]);
        x12 = __ldg(&x[c1.z]);
        x13 = __ldg(&x[c1.w]);
        if (use_smem) {
            w10 = s_pw[p1.x]; w11 = s_pw[p1.y]; w12 = s_pw[p1.z]; w13 = s_pw[p1.w];
        } else {
            w10 = __ldg(&Param_W[p1.x]); w11 = __ldg(&Param_W[p1.y]);
            w12 = __ldg(&Param_W[p1.z]); w13 = __ldg(&Param_W[p1.w]);
        }
    }

    atomicAdd(&out[r0.x], w00 * x00);
    atomicAdd(&out[r0.y], w01 * x01);
    atomicAdd(&out[r0.z], w02 * x02);
    atomicAdd(&out[r0.w], w03 * x03);
    if (has1) {
        atomicAdd(&out[r1.x], w10 * x10);
        atomicAdd(&out[r1.y], w11 * x11);
        atomicAdd(&out[r1.z], w12 * x12);
        atomicAdd(&out[r1.w], w13 * x13);
    }
}

// Tail path (E not divisible by 4)
__global__ void edge_scatter_tail_kernel(const float* __restrict__ x,
                                         const float* __restrict__ Param_W,
                                         const int* __restrict__ w_rows,
                                         const int* __restrict__ w_cols,
                                         const int* __restrict__ w_params,
                                         float* __restrict__ out,
                                         int start, int e) {
    int i = start + blockIdx.x * blockDim.x + threadIdx.x;
    if (i < e) {
        atomicAdd(&out[w_rows[i]], __ldg(&Param_W[w_params[i]]) * __ldg(&x[w_cols[i]]));
    }
}

extern "C" void kernel_launch(void* const* d_in, const int* in_sizes, int n_in,
                              void* d_out, int out_size) {
    // metadata order: x, Param_W, Param_b, w_rows, w_cols, w_params, b_params
    const float* x        = (const float*)d_in[0];
    const float* Param_W  = (const float*)d_in[1];
    const float* Param_b  = (const float*)d_in[2];
    const int*   w_rows   = (const int*)d_in[3];
    const int*   w_cols   = (const int*)d_in[4];
    const int*   w_params = (const int*)d_in[5];
    const int*   b_params = (const int*)d_in[6];
    float* out = (float*)d_out;

    int n   = out_size;       // N = 262144
    int e   = in_sizes[3];    // E = 16777216
    int npw = in_sizes[1];    // NPARAMS = 1280

    // 1) bias init
    {
        int threads = 256;
        int blocks = (n + threads - 1) / threads;
        bias_init_kernel<<<blocks, threads>>>(Param_b, b_params, out, n);
    }

    // 2) edge scatter, 8 edges per thread (2 int4 groups)
    int e4 = e / 4;
    if (e4 > 0) {
        int threads = 256;
        int nthreads_total = (e4 + 1) / 2;   // each thread covers 2 int4 groups
        int blocks = (nthreads_total + threads - 1) / threads;
        edge_scatter_kernel<<<blocks, threads>>>(
            x, Param_W,
            (const int4*)w_rows, (const int4*)w_cols, (const int4*)w_params,
            out, e4, npw);
    }

    int tail_start = e4 * 4;
    if (tail_start < e) {
        int rem = e - tail_start;
        int threads = 256;
        int blocks = (rem + threads - 1) / threads;
        edge_scatter_tail_kernel<<<blocks, threads>>>(
            x, Param_W, w_rows, w_cols, w_params, out, tail_start, e);
    }
}

// round 4
// speedup vs baseline: 1.0803x; 1.0803x over previous
#include <cuda_runtime.h>
#include <stdint.h>

// out[i] = Param_b[b_params[i]]  (bias init, also clears the 0xAA poison)
__global__ void bias_init_kernel(const float* __restrict__ Param_b,
                                 const int* __restrict__ b_params,
                                 float* __restrict__ out, int n) {
    int i = blockIdx.x * blockDim.x + threadIdx.x;
    if (i < n) {
        out[i] = __ldg(&Param_b[b_params[i]]);
    }
}

// x gather: keep x resident in L1 (evict_last priority).
__device__ __forceinline__ float ldg_evict_last(const float* p) {
    float v;
    asm volatile("ld.global.nc.L1::evict_last.f32 %0, [%1];"
                 : "=f"(v) : "l"(p));
    return v;
}

// Each thread handles 4 edges via int4 loads of the three index streams.
// Index streams: __ldcs (evict-first, zero reuse) so they don't flush x out
// of L1. x: evict_last. Param_W: tiny, normal __ldg (L1-resident anyway).
__global__ void __launch_bounds__(256) edge_scatter_kernel(
        const float* __restrict__ x,
        const float* __restrict__ Param_W,
        const int4* __restrict__ w_rows4,
        const int4* __restrict__ w_cols4,
        const int4* __restrict__ w_params4,
        float* __restrict__ out, int e4) {
    int i = blockIdx.x * blockDim.x + threadIdx.x;
    if (i >= e4) return;

    int4 r = __ldcs(&w_rows4[i]);
    int4 c = __ldcs(&w_cols4[i]);
    int4 p = __ldcs(&w_params4[i]);

    // Gather first (maximize MLP before the dependent atomics)
    float xw0 = ldg_evict_last(&x[c.x]);
    float xw1 = ldg_evict_last(&x[c.y]);
    float xw2 = ldg_evict_last(&x[c.z]);
    float xw3 = ldg_evict_last(&x[c.w]);
    float pw0 = __ldg(&Param_W[p.x]);
    float pw1 = __ldg(&Param_W[p.y]);
    float pw2 = __ldg(&Param_W[p.z]);
    float pw3 = __ldg(&Param_W[p.w]);

    atomicAdd(&out[r.x], pw0 * xw0);
    atomicAdd(&out[r.y], pw1 * xw1);
    atomicAdd(&out[r.z], pw2 * xw2);
    atomicAdd(&out[r.w], pw3 * xw3);
}

// Tail path (E not divisible by 4 — not expected here, but kept safe)
__global__ void edge_scatter_tail_kernel(const float* __restrict__ x,
                                         const float* __restrict__ Param_W,
                                         const int* __restrict__ w_rows,
                                         const int* __restrict__ w_cols,
                                         const int* __restrict__ w_params,
                                         float* __restrict__ out,
                                         int start, int e) {
    int i = start + blockIdx.x * blockDim.x + threadIdx.x;
    if (i < e) {
        atomicAdd(&out[w_rows[i]], __ldg(&Param_W[w_params[i]]) * __ldg(&x[w_cols[i]]));
    }
}

extern "C" void kernel_launch(void* const* d_in, const int* in_sizes, int n_in,
                              void* d_out, int out_size) {
    // metadata order: x, Param_W, Param_b, w_rows, w_cols, w_params, b_params
    const float* x        = (const float*)d_in[0];
    const float* Param_W  = (const float*)d_in[1];
    const float* Param_b  = (const float*)d_in[2];
    const int*   w_rows   = (const int*)d_in[3];
    const int*   w_cols   = (const int*)d_in[4];
    const int*   w_params = (const int*)d_in[5];
    const int*   b_params = (const int*)d_in[6];
    float* out = (float*)d_out;

    int n = out_size;          // N = 262144
    int e = in_sizes[3];       // E = 16777216

    // 1) bias init
    {
        int threads = 256;
        int blocks = (n + threads - 1) / threads;
        bias_init_kernel<<<blocks, threads>>>(Param_b, b_params, out, n);
    }

    // 2) edge scatter, 4 edges per thread
    int e4 = e / 4;
    if (e4 > 0) {
        int threads = 256;
        int blocks = (e4 + threads - 1) / threads;
        edge_scatter_kernel<<<blocks, threads>>>(
            x, Param_W,
            (const int4*)w_rows, (const int4*)w_cols, (const int4*)w_params,
            out, e4);
    }

    int tail_start = e4 * 4;
    if (tail_start < e) {
        int rem = e - tail_start;
        int threads = 256;
        int blocks = (rem + threads - 1) / threads;
        edge_scatter_tail_kernel<<<blocks, threads>>>(
            x, Param_W, w_rows, w_cols, w_params, out, tail_start, e);
    }
}